// round 4
// baseline (speedup 1.0000x reference)
#include <cuda_runtime.h>
#include <math.h>

#define NN 100000
#define NE 3200000
#define NF 512
#define NH 256
#define NC 16
#define NLAYER 8

// ---------------- device scratch (allocation-free rule: __device__ globals) ----
__device__ float g_h  [(size_t)NN * NH];
__device__ float g_h0 [(size_t)NN * NH];
__device__ float g_sup[(size_t)NN * NH];
__device__ int   g_rowptr[NN + 1];
__device__ int   g_cnt[NN];
__device__ int   g_srcs[NE];
__device__ float g_wsort[NE];

// ---------------- CSR build ---------------------------------------------------
__global__ void zero_cnt_kernel(int* __restrict__ cnt) {
    int i = blockIdx.x * blockDim.x + threadIdx.x;
    if (i < NN) cnt[i] = 0;
}

__global__ void hist_kernel(const int* __restrict__ dst, int* __restrict__ cnt) {
    int e = blockIdx.x * blockDim.x + threadIdx.x;
    if (e < NE) atomicAdd(&cnt[dst[e]], 1);
}

// single-block scan: counts (in cnt) -> exclusive offsets in rowptr, and cnt
// becomes the running cursor for the scatter pass.
__global__ __launch_bounds__(1024) void scan_kernel(int* __restrict__ cnt,
                                                    int* __restrict__ rowptr) {
    const int tid  = threadIdx.x;
    const int lane = tid & 31;
    const int wid  = tid >> 5;
    __shared__ int wsum[32];
    int carry = 0;
    for (int base = 0; base < NN; base += 1024) {
        int i = base + tid;
        int v = (i < NN) ? cnt[i] : 0;
        int incl = v;
#pragma unroll
        for (int off = 1; off < 32; off <<= 1) {
            int t = __shfl_up_sync(0xffffffffu, incl, off);
            if (lane >= off) incl += t;
        }
        if (lane == 31) wsum[wid] = incl;
        __syncthreads();
        if (wid == 0) {
            int s = wsum[lane];
#pragma unroll
            for (int off = 1; off < 32; off <<= 1) {
                int t = __shfl_up_sync(0xffffffffu, s, off);
                if (lane >= off) s += t;
            }
            wsum[lane] = s;
        }
        __syncthreads();
        int woff = (wid > 0) ? wsum[wid - 1] : 0;
        int excl = carry + woff + (incl - v);
        if (i < NN) { rowptr[i] = excl; cnt[i] = excl; }
        int total = wsum[31];
        __syncthreads();
        carry += total;
    }
    if (tid == 0) rowptr[NN] = carry;
}

__global__ void scatter_kernel(const int* __restrict__ src,
                               const int* __restrict__ dst,
                               const float* __restrict__ w,
                               int* __restrict__ cur,
                               int* __restrict__ osrc,
                               float* __restrict__ ow) {
    int e = blockIdx.x * blockDim.x + threadIdx.x;
    if (e < NE) {
        int d = dst[e];
        int p = atomicAdd(&cur[d], 1);
        osrc[p] = src[e];
        ow[p]   = w[e];
    }
}

// ---------------- SpMM: warp per row, fused 0.9*agg + 0.1*h0 ------------------
__device__ __forceinline__ void fmav(float4& a, float w, const float4& v) {
    a.x = fmaf(w, v.x, a.x); a.y = fmaf(w, v.y, a.y);
    a.z = fmaf(w, v.z, a.z); a.w = fmaf(w, v.w, a.w);
}

__global__ __launch_bounds__(256) void spmm_kernel(
    const int* __restrict__ rowptr, const int* __restrict__ srcs,
    const float* __restrict__ ws,
    const float* __restrict__ h, const float* __restrict__ h0,
    float* __restrict__ sup) {
    const int warp = threadIdx.x >> 5;
    const int lane = threadIdx.x & 31;
    const int row  = blockIdx.x * 8 + warp;
    if (row >= NN) return;
    const int beg = rowptr[row];
    const int end = rowptr[row + 1];
    float4 acc0 = make_float4(0.f, 0.f, 0.f, 0.f);
    float4 acc1 = acc0;
    const float4* hp = (const float4*)h;
    int e = beg;
    for (; e + 2 <= end; e += 2) {
        int   s0 = srcs[e],  s1 = srcs[e + 1];
        float wa = ws[e],    wb = ws[e + 1];
        const float4* p0 = hp + (size_t)s0 * 64;
        const float4* p1 = hp + (size_t)s1 * 64;
        float4 x0 = p0[lane], x1 = p0[32 + lane];
        float4 y0 = p1[lane], y1 = p1[32 + lane];
        fmav(acc0, wa, x0); fmav(acc1, wa, x1);
        fmav(acc0, wb, y0); fmav(acc1, wb, y1);
    }
    if (e < end) {
        int s0 = srcs[e]; float wa = ws[e];
        const float4* p0 = hp + (size_t)s0 * 64;
        float4 x0 = p0[lane], x1 = p0[32 + lane];
        fmav(acc0, wa, x0); fmav(acc1, wa, x1);
    }
    const float4* r = (const float4*)h0 + (size_t)row * 64;
    float4 r0 = r[lane], r1 = r[32 + lane];
    float4 o0, o1;
    o0.x = fmaf(0.9f, acc0.x, 0.1f * r0.x);
    o0.y = fmaf(0.9f, acc0.y, 0.1f * r0.y);
    o0.z = fmaf(0.9f, acc0.z, 0.1f * r0.z);
    o0.w = fmaf(0.9f, acc0.w, 0.1f * r0.w);
    o1.x = fmaf(0.9f, acc1.x, 0.1f * r1.x);
    o1.y = fmaf(0.9f, acc1.y, 0.1f * r1.y);
    o1.z = fmaf(0.9f, acc1.z, 0.1f * r1.z);
    o1.w = fmaf(0.9f, acc1.w, 0.1f * r1.w);
    float4* sp = (float4*)sup + (size_t)row * 64;
    sp[lane]      = o0;
    sp[32 + lane] = o1;
}

// ---------------- GEMM: 128x128x8 tiles, fma.rn.f32x2 (full-rate fp32) --------
#define BM 128
#define BN 128
#define BK 8

union F4U { float4 f; unsigned long long u[2]; };

// mode 0: h = h0 = relu(A@B + bias)            (A = x, K = 512)
// mode 1: h = relu(theta*(A@B) + (1-theta)*A + h)   (A = support, K = 256)
__global__ __launch_bounds__(256, 2) void gemm_kernel(
    const float* __restrict__ A, const float* __restrict__ B, int M, int K,
    const float* __restrict__ bias, const float* __restrict__ sup,
    float* __restrict__ hout, float* __restrict__ h0out,
    float theta, int mode) {
    __shared__ __align__(16) float Asd[2][BK][2 * BM];  // A duplicated pairwise
    __shared__ __align__(16) float Bs [2][BK][BN];

    const int tid = threadIdx.x;
    const int tx  = tid & 15;
    const int ty  = tid >> 4;
    const int rowBase = blockIdx.x * BM;
    const int nBase   = blockIdx.y * BN;

    const int aRow = tid >> 1;
    const int aCol = (tid & 1) * 4;
    const int bRow = tid >> 5;
    const int bCol = (tid & 31) * 4;

    unsigned long long acc[8][4];
#pragma unroll
    for (int i = 0; i < 8; i++)
#pragma unroll
        for (int j = 0; j < 4; j++) acc[i][j] = 0ULL;

    const int nk = K / BK;
    const float4 z4 = make_float4(0.f, 0.f, 0.f, 0.f);

    {   // tile 0
        int gr = rowBase + aRow;
        float4 av = (gr < M) ? *(const float4*)(A + (size_t)gr * K + aCol) : z4;
        float4 bv = *(const float4*)(B + (size_t)bRow * NH + nBase + bCol);
        float2 d;
        d.x = d.y = av.x; *(float2*)&Asd[0][aCol + 0][2 * aRow] = d;
        d.x = d.y = av.y; *(float2*)&Asd[0][aCol + 1][2 * aRow] = d;
        d.x = d.y = av.z; *(float2*)&Asd[0][aCol + 2][2 * aRow] = d;
        d.x = d.y = av.w; *(float2*)&Asd[0][aCol + 3][2 * aRow] = d;
        *(float4*)&Bs[0][bRow][bCol] = bv;
    }
    __syncthreads();

    for (int kt = 0; kt < nk; ++kt) {
        const int buf = kt & 1;
        float4 aN = z4, bN = z4;
        if (kt + 1 < nk) {
            int kb = (kt + 1) * BK;
            int gr = rowBase + aRow;
            aN = (gr < M) ? *(const float4*)(A + (size_t)gr * K + kb + aCol) : z4;
            bN = *(const float4*)(B + (size_t)(kb + bRow) * NH + nBase + bCol);
        }
#pragma unroll
        for (int k = 0; k < BK; ++k) {
            F4U a0, a1, a2, a3, b0, b1;
            const float4* ap4 = (const float4*)&Asd[buf][k][ty * 16];
            a0.f = ap4[0]; a1.f = ap4[1]; a2.f = ap4[2]; a3.f = ap4[3];
            const float4* bp4 = (const float4*)&Bs[buf][k][tx * 8];
            b0.f = bp4[0]; b1.f = bp4[1];
            unsigned long long av[8] = {a0.u[0], a0.u[1], a1.u[0], a1.u[1],
                                        a2.u[0], a2.u[1], a3.u[0], a3.u[1]};
            unsigned long long bv[4] = {b0.u[0], b0.u[1], b1.u[0], b1.u[1]};
#pragma unroll
            for (int i = 0; i < 8; i++)
#pragma unroll
                for (int j = 0; j < 4; j++)
                    asm("fma.rn.f32x2 %0, %1, %2, %0;"
                        : "+l"(acc[i][j]) : "l"(av[i]), "l"(bv[j]));
        }
        if (kt + 1 < nk) {
            const int nb = buf ^ 1;
            float2 d;
            d.x = d.y = aN.x; *(float2*)&Asd[nb][aCol + 0][2 * aRow] = d;
            d.x = d.y = aN.y; *(float2*)&Asd[nb][aCol + 1][2 * aRow] = d;
            d.x = d.y = aN.z; *(float2*)&Asd[nb][aCol + 2][2 * aRow] = d;
            d.x = d.y = aN.w; *(float2*)&Asd[nb][aCol + 3][2 * aRow] = d;
            *(float4*)&Bs[nb][bRow][bCol] = bN;
            __syncthreads();
        }
    }

    const float omt = 1.0f - theta;
#pragma unroll
    for (int i = 0; i < 8; i++) {
        int grow = rowBase + ty * 8 + i;
        if (grow >= M) break;
        size_t rb = (size_t)grow * NH + nBase + tx * 8;
        if (mode == 0) {
#pragma unroll
            for (int j = 0; j < 4; j++) {
                float lo = __uint_as_float((unsigned)(acc[i][j]));
                float hi = __uint_as_float((unsigned)(acc[i][j] >> 32));
                int gc = nBase + tx * 8 + 2 * j;
                float v0 = fmaxf(lo + __ldg(&bias[gc]),     0.f);
                float v1 = fmaxf(hi + __ldg(&bias[gc + 1]), 0.f);
                float2 val = make_float2(v0, v1);
                *(float2*)(hout  + rb + 2 * j) = val;
                *(float2*)(h0out + rb + 2 * j) = val;
            }
        } else {
#pragma unroll
            for (int j = 0; j < 4; j++) {
                float lo = __uint_as_float((unsigned)(acc[i][j]));
                float hi = __uint_as_float((unsigned)(acc[i][j] >> 32));
                float2 s  = *(const float2*)(sup  + rb + 2 * j);
                float2 ho = *(const float2*)(hout + rb + 2 * j);
                float v0 = fmaxf(fmaf(theta, lo, fmaf(omt, s.x, ho.x)), 0.f);
                float v1 = fmaxf(fmaf(theta, hi, fmaf(omt, s.y, ho.y)), 0.f);
                *(float2*)(hout + rb + 2 * j) = make_float2(v0, v1);
            }
        }
    }
}

// ---------------- final fc + sigmoid ------------------------------------------
__global__ __launch_bounds__(128) void fc1_kernel(const float* __restrict__ h,
                                                  const float* __restrict__ w1,
                                                  const float* __restrict__ b1,
                                                  float* __restrict__ out) {
    __shared__ float ws[NH * NC];
    __shared__ float bs[NC];
    const int tid = threadIdx.x;
    for (int i = tid; i < NH * NC; i += 128) ws[i] = w1[i];
    if (tid < NC) bs[tid] = b1[tid];
    __syncthreads();
    const int col = tid & 15;
    const int r   = tid >> 4;
    const int row = blockIdx.x * 8 + r;
    if (row >= NN) return;
    const float* hr = h + (size_t)row * NH;
    float acc = 0.f;
#pragma unroll 4
    for (int k = 0; k < NH; k += 4) {
        float4 hv = *(const float4*)(hr + k);
        acc = fmaf(hv.x, ws[(k + 0) * NC + col], acc);
        acc = fmaf(hv.y, ws[(k + 1) * NC + col], acc);
        acc = fmaf(hv.z, ws[(k + 2) * NC + col], acc);
        acc = fmaf(hv.w, ws[(k + 3) * NC + col], acc);
    }
    acc += bs[col];
    out[(size_t)row * NC + col] = 1.0f / (1.0f + expf(-acc));
}

// ---------------- launch -------------------------------------------------------
extern "C" void kernel_launch(void* const* d_in, const int* in_sizes, int n_in,
                              void* d_out, int out_size) {
    const float* x     = (const float*)d_in[0];
    const int*   esrc  = (const int*)  d_in[1];
    const int*   edst  = (const int*)  d_in[2];
    const float* ew    = (const float*)d_in[3];
    const float* w0    = (const float*)d_in[4];
    const float* b0    = (const float*)d_in[5];
    const float* convw = (const float*)d_in[6];
    const float* w1    = (const float*)d_in[7];
    const float* b1    = (const float*)d_in[8];
    float* out = (float*)d_out;

    void *ph, *ph0, *psup, *prp, *pcnt, *psrc, *pws;
    cudaGetSymbolAddress(&ph,   g_h);
    cudaGetSymbolAddress(&ph0,  g_h0);
    cudaGetSymbolAddress(&psup, g_sup);
    cudaGetSymbolAddress(&prp,  g_rowptr);
    cudaGetSymbolAddress(&pcnt, g_cnt);
    cudaGetSymbolAddress(&psrc, g_srcs);
    cudaGetSymbolAddress(&pws,  g_wsort);
    float* h      = (float*)ph;
    float* h0     = (float*)ph0;
    float* sup    = (float*)psup;
    int*   rowptr = (int*)prp;
    int*   cnt    = (int*)pcnt;
    int*   srcs   = (int*)psrc;
    float* wsort  = (float*)pws;

    // CSR-by-dst build (deterministic up to fp-add order within a row)
    zero_cnt_kernel<<<(NN + 255) / 256, 256>>>(cnt);
    hist_kernel    <<<(NE + 255) / 256, 256>>>(edst, cnt);
    scan_kernel    <<<1, 1024>>>(cnt, rowptr);
    scatter_kernel <<<(NE + 255) / 256, 256>>>(esrc, edst, ew, cnt, srcs, wsort);

    dim3 gg((NN + BM - 1) / BM, NH / BN);

    // h = h0 = relu(x @ w0 + b0)
    gemm_kernel<<<gg, 256>>>(x, w0, NN, NF, b0, nullptr, h, h0, 0.f, 0);

    for (int i = 0; i < NLAYER; ++i) {
        // support = 0.9 * spmm(h) + 0.1 * h0
        spmm_kernel<<<(NN + 7) / 8, 256>>>(rowptr, srcs, wsort, h, h0, sup);
        float theta = (float)log(0.5 / (double)(i + 1) + 1.0);
        // h = relu(theta*(support@W_i) + (1-theta)*support + h)
        gemm_kernel<<<gg, 256>>>(sup, convw + (size_t)i * NH * NH, NN, NH,
                                 nullptr, sup, h, nullptr, theta, 1);
    }

    // out = sigmoid(h @ w1 + b1)
    fc1_kernel<<<(NN + 7) / 8, 128>>>(h, w1, b1, out);
}